// round 12
// baseline (speedup 1.0000x reference)
#include <cuda_runtime.h>
#include <math.h>

// Problem constants (fixed shapes from setup_inputs)
#define NB 2
#define CH 128
#define HH 128
#define WW 128
#define HL 64
#define WL 64
#define PLANE (HH*WW)          // 16384
#define IMG   (CH*PLANE)

#define NSPLIT 4               // channel splits for gating conv
#define CPS (CH/NSPLIT)        // 32
#define NGRP 8                 // channel groups for sim/agg
#define GSIM (CH/NGRP)         // 16

// Scratch (module-load allocated; no runtime allocs)
__device__ float g_lrup[NB*IMG];
__device__ float g_key [NB*IMG];
__device__ float g_val [NB*IMG];
__device__ float g_qry [NB*IMG];
__device__ float g_s4  [NSPLIT*NB*2*9*PLANE];   // partial gating tap maps
__device__ float g_psim[NB*NGRP*25*PLANE];      // partial sims (26MB, L2-resident)
__device__ float g_w   [NB*25*PLANE];           // gated softmax weights

// ---------------------------------------------------------------------------
// Kernel 1: bilinear upsample (align_corners=True) 64x64 -> 128x128
// ---------------------------------------------------------------------------
__global__ void k_lrup(const float* __restrict__ lr) {
    int idx = blockIdx.x * blockDim.x + threadIdx.x;
    int w  = idx & (WW-1);
    int h  = (idx >> 7) & (HH-1);
    int nc = idx >> 14;

    float ys = (float)(h * (HL-1)) / (float)(HH-1);
    float xs = (float)(w * (WL-1)) / (float)(WW-1);
    int y0 = (int)floorf(ys);
    int x0 = (int)floorf(xs);
    int y1 = min(y0 + 1, HL-1);
    int x1 = min(x0 + 1, WL-1);
    float wy = ys - (float)y0;
    float wx = xs - (float)x0;

    const float* p = lr + nc * (HL*WL);
    float a = p[y0*WL + x0];
    float b = p[y0*WL + x1];
    float c = p[y1*WL + x0];
    float d = p[y1*WL + x1];
    float top = a + (b - a) * wx;
    float bot = c + (d - c) * wx;
    g_lrup[idx] = top + (bot - top) * wy;
}

// ---------------------------------------------------------------------------
// Kernel 2: three depthwise 3x3 convs, 4 horizontal px/thread, float4 I/O.
// ---------------------------------------------------------------------------
__global__ __launch_bounds__(128) void k_qkv(const float* __restrict__ hr,
                      const float* __restrict__ wq, const float* __restrict__ bq,
                      const float* __restrict__ wk, const float* __restrict__ bk,
                      const float* __restrict__ wv, const float* __restrict__ bv) {
    int idx = blockIdx.x * 128 + threadIdx.x;   // (n, c, h, w4)
    int w4 = idx & 31;
    int h  = (idx >> 5) & (HH-1);
    int c  = (idx >> 12) & (CH-1);
    int n  = idx >> 19;
    int w0 = w4 * 4;

    const float* ph = hr     + (n*CH + c) * PLANE;
    const float* pl = g_lrup + (n*CH + c) * PLANE;

    float xh[3][6], xl[3][6];
    #pragma unroll
    for (int i = 0; i < 3; i++) {
        int hh = h + i - 1;
        bool hv = (hh >= 0) && (hh < HH);
        if (hv) {
            int rb = hh * WW;
            float lh = (w0 - 1 >= 0) ? ph[rb + w0 - 1] : 0.f;
            float ll = (w0 - 1 >= 0) ? pl[rb + w0 - 1] : 0.f;
            float4 mh = *(const float4*)&ph[rb + w0];
            float4 ml = *(const float4*)&pl[rb + w0];
            float rh = (w0 + 4 < WW) ? ph[rb + w0 + 4] : 0.f;
            float rl = (w0 + 4 < WW) ? pl[rb + w0 + 4] : 0.f;
            xh[i][0]=lh; xh[i][1]=mh.x; xh[i][2]=mh.y; xh[i][3]=mh.z; xh[i][4]=mh.w; xh[i][5]=rh;
            xl[i][0]=ll; xl[i][1]=ml.x; xl[i][2]=ml.y; xl[i][3]=ml.z; xl[i][4]=ml.w; xl[i][5]=rl;
        } else {
            #pragma unroll
            for (int j = 0; j < 6; j++) { xh[i][j] = 0.f; xl[i][j] = 0.f; }
        }
    }

    float wkr[9], wvr[9], wqr[9];
    #pragma unroll
    for (int t = 0; t < 9; t++) {
        wkr[t] = wk[c*9 + t];
        wvr[t] = wv[c*9 + t];
        wqr[t] = wq[c*9 + t];
    }
    float bkc = bk[c], bvc = bv[c], bqc = bq[c];

    float4 ok, ov, oq;
    float* okp = (float*)&ok; float* ovp = (float*)&ov; float* oqp = (float*)&oq;
    #pragma unroll
    for (int p = 0; p < 4; p++) {
        float acck = bkc, accv = bvc, accq = bqc;
        #pragma unroll
        for (int i = 0; i < 3; i++)
            #pragma unroll
            for (int j = 0; j < 3; j++) {
                acck += xh[i][p+j] * wkr[i*3+j];
                accv += xh[i][p+j] * wvr[i*3+j];
                accq += xl[i][p+j] * wqr[i*3+j];
            }
        okp[p] = acck; ovp[p] = accv; oqp[p] = accq;
    }
    int gi = ((n*CH + c) << 14) + h*WW + w0;
    *(float4*)&g_key[gi] = ok;
    *(float4*)&g_val[gi] = ov;
    *(float4*)&g_qry[gi] = oq;
}

// ---------------------------------------------------------------------------
// Kernel 3: partial gating tap maps, 4-way channel split, 2 px/thread.
// ---------------------------------------------------------------------------
__global__ __launch_bounds__(128) void k_s(const float* __restrict__ wa) {
    __shared__ __align__(16) float swa[CPS*36];   // 4.5 KB

    int tid = threadIdx.x;
    int sp  = blockIdx.y;
    int cbase = sp * CPS;

    for (int j = tid; j < CPS*36; j += 128) {
        int c   = j / 36;
        int r   = j % 36;
        int grp = r / 9;             // 0:q/o0 1:k/o0 2:q/o1 3:k/o1
        int t   = r % 9;
        int o   = grp >> 1;
        int ci  = cbase + c + ((grp & 1) ? CH : 0);
        swa[j] = wa[(o*2*CH + ci)*9 + t];
    }
    __syncthreads();

    int px0 = blockIdx.x * 256 + tid;           // pixel A
    int px1 = px0 + 128;                        // pixel B (same n: 256|16384)
    int n   = px0 >> 14;
    int pixA = px0 & (PLANE-1);
    int pixB = px1 & (PLANE-1);

    float accA[18], accB[18];
    #pragma unroll
    for (int t = 0; t < 18; t++) { accA[t] = 0.f; accB[t] = 0.f; }

    int baseA = n*CH*PLANE + cbase*PLANE + pixA;
    int baseB = n*CH*PLANE + cbase*PLANE + pixB;
    for (int c = 0; c < CPS; c++) {
        float qA = g_qry[baseA + c*PLANE];
        float kA = g_key[baseA + c*PLANE];
        float qB = g_qry[baseB + c*PLANE];
        float kB = g_key[baseB + c*PLANE];

        float wreg[36];
        float4* wr4 = (float4*)wreg;
        const float4* sw4 = (const float4*)(swa + c*36);
        #pragma unroll
        for (int i = 0; i < 9; i++) wr4[i] = sw4[i];

        #pragma unroll
        for (int t = 0; t < 9; t++) {
            accA[t]     += qA * wreg[t]    + kA * wreg[9+t];
            accA[9 + t] += qA * wreg[18+t] + kA * wreg[27+t];
            accB[t]     += qB * wreg[t]    + kB * wreg[9+t];
            accB[9 + t] += qB * wreg[18+t] + kB * wreg[27+t];
        }
    }

    #pragma unroll
    for (int o = 0; o < 2; o++)
        #pragma unroll
        for (int t = 0; t < 9; t++) {
            int s = (((sp*NB + n)*2 + o)*9 + t) << 14;
            g_s4[s + pixA] = accA[o*9 + t];
            g_s4[s + pixB] = accB[o*9 + t];
        }
}

// ---------------------------------------------------------------------------
// Tile geometry for window kernels: 64x8 px, 256 threads, warp = pixel row.
// ---------------------------------------------------------------------------
#define STW 64
#define STH 8
#define SHW (STW+4)   // 68
#define SHH (STH+4)   // 12

// div-free halo fill: warp covers rows {warp, warp+8}, lane covers float2 j,j+32
__device__ __forceinline__ void fill_tile(float st[GSIM][SHH][SHW],
                                          const float* gsrc, int nc_base,
                                          int h0, int w0, int warp, int lane) {
    #pragma unroll 4
    for (int c = 0; c < GSIM; c++) {
        const float* src = gsrc + ((nc_base + c) << 14);
        #pragma unroll
        for (int r2 = 0; r2 < 2; r2++) {
            int yy = warp + 8*r2;
            if (yy < SHH) {
                int gh = h0 + yy - 2;
                bool hv = (gh >= 0) && (gh < HH);
                #pragma unroll
                for (int jo = 0; jo < 2; jo++) {
                    int j = lane + 32*jo;
                    if (j < 34) {
                        int xx = 2*j;
                        int gw = w0 + xx - 2;
                        float2 v = make_float2(0.f, 0.f);
                        if (hv) {
                            if (gw >= 0 && gw + 1 < WW) {
                                v = *(const float2*)&src[gh*WW + gw];
                            } else {
                                if (gw >= 0 && gw < WW)         v.x = src[gh*WW + gw];
                                if (gw + 1 >= 0 && gw + 1 < WW) v.y = src[gh*WW + gw + 1];
                            }
                        }
                        *(float2*)&st[c][yy][xx] = v;
                    }
                }
            }
        }
    }
}

// ---------------------------------------------------------------------------
// Kernel 4: partial similarities, 16-ch group, dy-outer, 2 px/thread.
// Reg budget 85 (3 blocks/SM) for deeper LDS pipelining.
// ---------------------------------------------------------------------------
__global__ __launch_bounds__(256,3) void k_sim() {
    __shared__ __align__(16) float st[GSIM][SHH][SHW];   // 52.2 KB

    int lane = threadIdx.x & 31;
    int warp = threadIdx.x >> 5;
    int w0 = blockIdx.x * STW;
    int h0 = blockIdx.y * STH;
    int g  = blockIdx.z & (NGRP-1);
    int n  = blockIdx.z >> 3;
    int c0 = g * GSIM;
    int h  = h0 + warp;
    int wA = w0 + 2*lane;
    int pixA = h*WW + wA;

    fill_tile(st, g_key, n*CH + c0, h0, w0, warp, lane);

    // q resident in regs (16 independent LDG.64)
    float2 q2[GSIM];
    #pragma unroll
    for (int c = 0; c < GSIM; c++)
        q2[c] = *(const float2*)&g_qry[((n*CH + c0 + c) << 14) + pixA];

    __syncthreads();

    #pragma unroll
    for (int dy = 0; dy < 5; dy++) {
        float sA[5], sB[5];
        #pragma unroll
        for (int t = 0; t < 5; t++) { sA[t] = 0.f; sB[t] = 0.f; }

        #pragma unroll
        for (int c = 0; c < GSIM; c++) {
            float2 t0 = *(float2*)&st[c][warp+dy][2*lane + 0];
            float2 t1 = *(float2*)&st[c][warp+dy][2*lane + 2];
            float2 t2 = *(float2*)&st[c][warp+dy][2*lane + 4];
            sA[0] += q2[c].x * t0.x;
            sA[1] += q2[c].x * t0.y;
            sA[2] += q2[c].x * t1.x;
            sA[3] += q2[c].x * t1.y;
            sA[4] += q2[c].x * t2.x;
            sB[0] += q2[c].y * t0.y;
            sB[1] += q2[c].y * t1.x;
            sB[2] += q2[c].y * t1.y;
            sB[3] += q2[c].y * t2.x;
            sB[4] += q2[c].y * t2.y;
        }

        #pragma unroll
        for (int dx = 0; dx < 5; dx++) {
            float2 o; o.x = sA[dx]; o.y = sB[dx];
            *(float2*)&g_psim[(((n*NGRP + g)*25 + dy*5 + dx) << 14) + pixA] = o;
        }
    }
}

// ---------------------------------------------------------------------------
// Kernel 5: fused gate + softmax. Per pixel:
//   dyn[o] = sigmoid(ba[o] + sum_sp sum_tap shift(s4))
//   w = dyn0 * softmax(sum_g psim);  w[12] += dyn1
// ---------------------------------------------------------------------------
__global__ __launch_bounds__(256) void k_smax(const float* __restrict__ ba) {
    int idx = blockIdx.x * 256 + threadIdx.x;     // (n, pix)
    int pix = idx & (PLANE-1);
    int n   = idx >> 14;
    int w = pix & (WW-1);
    int h = pix >> 7;

    // inline dyn computation (3x3 gather over 4 split partials, both outputs)
    float acc0 = ba[0];
    float acc1 = ba[1];
    #pragma unroll
    for (int sp = 0; sp < NSPLIT; sp++) {
        #pragma unroll
        for (int i = 0; i < 3; i++) {
            int hh = h + i - 1;
            if (hh < 0 || hh >= HH) continue;
            #pragma unroll
            for (int j = 0; j < 3; j++) {
                int ww2 = w + j - 1;
                if (ww2 < 0 || ww2 >= WW) continue;
                int t = i*3 + j;
                int off = hh*WW + ww2;
                acc0 += g_s4[((((sp*NB + n)*2 + 0)*9 + t) << 14) + off];
                acc1 += g_s4[((((sp*NB + n)*2 + 1)*9 + t) << 14) + off];
            }
        }
    }
    float d0 = 1.f / (1.f + __expf(-acc0));
    float d1 = 1.f / (1.f + __expf(-acc1));

    float s[25];
    #pragma unroll
    for (int k = 0; k < 25; k++) s[k] = 0.f;
    #pragma unroll
    for (int g = 0; g < NGRP; g++)
        #pragma unroll
        for (int k = 0; k < 25; k++)
            s[k] += g_psim[(((n*NGRP + g)*25 + k) << 14) + pix];

    float m = s[0];
    #pragma unroll
    for (int k = 1; k < 25; k++) m = fmaxf(m, s[k]);
    float ssum = 0.f;
    #pragma unroll
    for (int k = 0; k < 25; k++) { s[k] = __expf(s[k] - m); ssum += s[k]; }

    float scale = d0 / ssum;
    #pragma unroll
    for (int k = 0; k < 25; k++) {
        float wv = s[k] * scale;
        if (k == 12) wv += d1;
        g_w[((n*25 + k) << 14) + pix] = wv;
    }
}

// ---------------------------------------------------------------------------
// Kernel 6: value aggregation, dy-outer, 2 px/thread, reg budget 85.
// ---------------------------------------------------------------------------
__global__ __launch_bounds__(256,3) void k_agg(float* __restrict__ out) {
    __shared__ __align__(16) float st[GSIM][SHH][SHW];   // 52.2 KB

    int lane = threadIdx.x & 31;
    int warp = threadIdx.x >> 5;
    int w0 = blockIdx.x * STW;
    int h0 = blockIdx.y * STH;
    int g  = blockIdx.z & (NGRP-1);
    int n  = blockIdx.z >> 3;
    int c0 = g * GSIM;
    int h  = h0 + warp;
    int wA = w0 + 2*lane;
    int pixA = h*WW + wA;

    fill_tile(st, g_val, n*CH + c0, h0, w0, warp, lane);

    float aA[GSIM], aB[GSIM];
    #pragma unroll
    for (int c = 0; c < GSIM; c++) { aA[c] = 0.f; aB[c] = 0.f; }

    __syncthreads();

    #pragma unroll
    for (int dy = 0; dy < 5; dy++) {
        float wgA[5], wgB[5];
        #pragma unroll
        for (int dx = 0; dx < 5; dx++) {
            float2 wv = *(const float2*)&g_w[((n*25 + dy*5 + dx) << 14) + pixA];
            wgA[dx] = wv.x; wgB[dx] = wv.y;
        }
        #pragma unroll
        for (int c = 0; c < GSIM; c++) {
            float2 t0 = *(float2*)&st[c][warp+dy][2*lane + 0];
            float2 t1 = *(float2*)&st[c][warp+dy][2*lane + 2];
            float2 t2 = *(float2*)&st[c][warp+dy][2*lane + 4];
            aA[c] += wgA[0]*t0.x + wgA[1]*t0.y + wgA[2]*t1.x + wgA[3]*t1.y + wgA[4]*t2.x;
            aB[c] += wgB[0]*t0.y + wgB[1]*t1.x + wgB[2]*t1.y + wgB[3]*t2.x + wgB[4]*t2.y;
        }
    }

    #pragma unroll
    for (int c = 0; c < GSIM; c++) {
        int gi = ((n*CH + c0 + c) << 14) + pixA;
        float2 lu = *(const float2*)&g_lrup[gi];
        float2 o; o.x = lu.x + aA[c]; o.y = lu.y + aB[c];
        *(float2*)&out[gi] = o;
    }
}

// ---------------------------------------------------------------------------
extern "C" void kernel_launch(void* const* d_in, const int* in_sizes, int n_in,
                              void* d_out, int out_size) {
    const float* hr = (const float*)d_in[0];
    const float* lr = (const float*)d_in[1];
    const float* wq = (const float*)d_in[2];
    const float* bq = (const float*)d_in[3];
    const float* wk = (const float*)d_in[4];
    const float* bk = (const float*)d_in[5];
    const float* wv = (const float*)d_in[6];
    const float* bv = (const float*)d_in[7];
    const float* wa = (const float*)d_in[8];
    const float* ba = (const float*)d_in[9];
    float* out = (float*)d_out;

    k_lrup<<<(NB*IMG)/256, 256>>>(lr);
    k_qkv <<<(NB*IMG/4)/128, 128>>>(hr, wq, bq, wk, bk, wv, bv);
    k_s   <<<dim3((NB*PLANE/2)/128, NSPLIT), 128>>>(wa);
    // k_sim stays 4th so the fixed ncu window lands on it
    k_sim <<<dim3(WW/STW, HH/STH, NB*NGRP), 256>>>();
    k_smax<<<(NB*PLANE)/256, 256>>>(ba);
    k_agg <<<dim3(WW/STW, HH/STH, NB*NGRP), 256>>>(out);
}

// round 13
// speedup vs baseline: 1.2656x; 1.2656x over previous
#include <cuda_runtime.h>
#include <math.h>

// Problem constants (fixed shapes from setup_inputs)
#define NB 2
#define CH 128
#define HH 128
#define WW 128
#define HL 64
#define WL 64
#define PLANE (HH*WW)          // 16384
#define IMG   (CH*PLANE)

#define NSPLIT 4               // channel splits for gating conv
#define CPS (CH/NSPLIT)        // 32
#define NGRP 8                 // channel groups for sim/agg
#define GSIM (CH/NGRP)         // 16

// Scratch (module-load allocated; no runtime allocs)
__device__ float g_lrup[NB*IMG];
__device__ float g_key [NB*IMG];
__device__ float g_val [NB*IMG];
__device__ float g_qry [NB*IMG];
__device__ float g_s4  [NSPLIT*NB*2*9*PLANE];   // partial gating tap maps
__device__ float g_psim[NB*NGRP*25*PLANE];      // partial sims (26MB, L2-resident)
__device__ float g_w   [NB*25*PLANE];           // gated softmax weights

// ---------------------------------------------------------------------------
// Kernel 1: bilinear upsample (align_corners=True) 64x64 -> 128x128
// ---------------------------------------------------------------------------
__global__ void k_lrup(const float* __restrict__ lr) {
    int idx = blockIdx.x * blockDim.x + threadIdx.x;
    int w  = idx & (WW-1);
    int h  = (idx >> 7) & (HH-1);
    int nc = idx >> 14;

    float ys = (float)(h * (HL-1)) / (float)(HH-1);
    float xs = (float)(w * (WL-1)) / (float)(WW-1);
    int y0 = (int)floorf(ys);
    int x0 = (int)floorf(xs);
    int y1 = min(y0 + 1, HL-1);
    int x1 = min(x0 + 1, WL-1);
    float wy = ys - (float)y0;
    float wx = xs - (float)x0;

    const float* p = lr + nc * (HL*WL);
    float a = p[y0*WL + x0];
    float b = p[y0*WL + x1];
    float c = p[y1*WL + x0];
    float d = p[y1*WL + x1];
    float top = a + (b - a) * wx;
    float bot = c + (d - c) * wx;
    g_lrup[idx] = top + (bot - top) * wy;
}

// ---------------------------------------------------------------------------
// Kernel 2: three depthwise 3x3 convs, 4 horizontal px/thread, float4 I/O.
// ---------------------------------------------------------------------------
__global__ __launch_bounds__(128) void k_qkv(const float* __restrict__ hr,
                      const float* __restrict__ wq, const float* __restrict__ bq,
                      const float* __restrict__ wk, const float* __restrict__ bk,
                      const float* __restrict__ wv, const float* __restrict__ bv) {
    int idx = blockIdx.x * 128 + threadIdx.x;   // (n, c, h, w4)
    int w4 = idx & 31;
    int h  = (idx >> 5) & (HH-1);
    int c  = (idx >> 12) & (CH-1);
    int n  = idx >> 19;
    int w0 = w4 * 4;

    const float* ph = hr     + (n*CH + c) * PLANE;
    const float* pl = g_lrup + (n*CH + c) * PLANE;

    float xh[3][6], xl[3][6];
    #pragma unroll
    for (int i = 0; i < 3; i++) {
        int hh = h + i - 1;
        bool hv = (hh >= 0) && (hh < HH);
        if (hv) {
            int rb = hh * WW;
            float lh = (w0 - 1 >= 0) ? ph[rb + w0 - 1] : 0.f;
            float ll = (w0 - 1 >= 0) ? pl[rb + w0 - 1] : 0.f;
            float4 mh = *(const float4*)&ph[rb + w0];
            float4 ml = *(const float4*)&pl[rb + w0];
            float rh = (w0 + 4 < WW) ? ph[rb + w0 + 4] : 0.f;
            float rl = (w0 + 4 < WW) ? pl[rb + w0 + 4] : 0.f;
            xh[i][0]=lh; xh[i][1]=mh.x; xh[i][2]=mh.y; xh[i][3]=mh.z; xh[i][4]=mh.w; xh[i][5]=rh;
            xl[i][0]=ll; xl[i][1]=ml.x; xl[i][2]=ml.y; xl[i][3]=ml.z; xl[i][4]=ml.w; xl[i][5]=rl;
        } else {
            #pragma unroll
            for (int j = 0; j < 6; j++) { xh[i][j] = 0.f; xl[i][j] = 0.f; }
        }
    }

    float wkr[9], wvr[9], wqr[9];
    #pragma unroll
    for (int t = 0; t < 9; t++) {
        wkr[t] = wk[c*9 + t];
        wvr[t] = wv[c*9 + t];
        wqr[t] = wq[c*9 + t];
    }
    float bkc = bk[c], bvc = bv[c], bqc = bq[c];

    float4 ok, ov, oq;
    float* okp = (float*)&ok; float* ovp = (float*)&ov; float* oqp = (float*)&oq;
    #pragma unroll
    for (int p = 0; p < 4; p++) {
        float acck = bkc, accv = bvc, accq = bqc;
        #pragma unroll
        for (int i = 0; i < 3; i++)
            #pragma unroll
            for (int j = 0; j < 3; j++) {
                acck += xh[i][p+j] * wkr[i*3+j];
                accv += xh[i][p+j] * wvr[i*3+j];
                accq += xl[i][p+j] * wqr[i*3+j];
            }
        okp[p] = acck; ovp[p] = accv; oqp[p] = accq;
    }
    int gi = ((n*CH + c) << 14) + h*WW + w0;
    *(float4*)&g_key[gi] = ok;
    *(float4*)&g_val[gi] = ov;
    *(float4*)&g_qry[gi] = oq;
}

// ---------------------------------------------------------------------------
// Kernel 3: partial gating tap maps, 4-way channel split, 2 px/thread.
// ---------------------------------------------------------------------------
__global__ __launch_bounds__(128) void k_s(const float* __restrict__ wa) {
    __shared__ __align__(16) float swa[CPS*36];   // 4.5 KB

    int tid = threadIdx.x;
    int sp  = blockIdx.y;
    int cbase = sp * CPS;

    for (int j = tid; j < CPS*36; j += 128) {
        int c   = j / 36;
        int r   = j % 36;
        int grp = r / 9;             // 0:q/o0 1:k/o0 2:q/o1 3:k/o1
        int t   = r % 9;
        int o   = grp >> 1;
        int ci  = cbase + c + ((grp & 1) ? CH : 0);
        swa[j] = wa[(o*2*CH + ci)*9 + t];
    }
    __syncthreads();

    int px0 = blockIdx.x * 256 + tid;           // pixel A
    int px1 = px0 + 128;                        // pixel B (same n: 256|16384)
    int n   = px0 >> 14;
    int pixA = px0 & (PLANE-1);
    int pixB = px1 & (PLANE-1);

    float accA[18], accB[18];
    #pragma unroll
    for (int t = 0; t < 18; t++) { accA[t] = 0.f; accB[t] = 0.f; }

    int baseA = n*CH*PLANE + cbase*PLANE + pixA;
    int baseB = n*CH*PLANE + cbase*PLANE + pixB;
    for (int c = 0; c < CPS; c++) {
        float qA = g_qry[baseA + c*PLANE];
        float kA = g_key[baseA + c*PLANE];
        float qB = g_qry[baseB + c*PLANE];
        float kB = g_key[baseB + c*PLANE];

        float wreg[36];
        float4* wr4 = (float4*)wreg;
        const float4* sw4 = (const float4*)(swa + c*36);
        #pragma unroll
        for (int i = 0; i < 9; i++) wr4[i] = sw4[i];

        #pragma unroll
        for (int t = 0; t < 9; t++) {
            accA[t]     += qA * wreg[t]    + kA * wreg[9+t];
            accA[9 + t] += qA * wreg[18+t] + kA * wreg[27+t];
            accB[t]     += qB * wreg[t]    + kB * wreg[9+t];
            accB[9 + t] += qB * wreg[18+t] + kB * wreg[27+t];
        }
    }

    #pragma unroll
    for (int o = 0; o < 2; o++)
        #pragma unroll
        for (int t = 0; t < 9; t++) {
            int s = (((sp*NB + n)*2 + o)*9 + t) << 14;
            g_s4[s + pixA] = accA[o*9 + t];
            g_s4[s + pixB] = accB[o*9 + t];
        }
}

// ---------------------------------------------------------------------------
// Tile geometry for window kernels: 64x8 px, 256 threads, warp = pixel row.
// (round-9 proven configuration)
// ---------------------------------------------------------------------------
#define STW 64
#define STH 8
#define SHW (STW+4)   // 68
#define SHH (STH+4)   // 12

// div-free halo fill: warp covers rows {warp, warp+8}, lane covers float2 j,j+32
__device__ __forceinline__ void fill_tile(float st[GSIM][SHH][SHW],
                                          const float* gsrc, int nc_base,
                                          int h0, int w0, int warp, int lane) {
    #pragma unroll 4
    for (int c = 0; c < GSIM; c++) {
        const float* src = gsrc + ((nc_base + c) << 14);
        #pragma unroll
        for (int r2 = 0; r2 < 2; r2++) {
            int yy = warp + 8*r2;
            if (yy < SHH) {
                int gh = h0 + yy - 2;
                bool hv = (gh >= 0) && (gh < HH);
                #pragma unroll
                for (int jo = 0; jo < 2; jo++) {
                    int j = lane + 32*jo;
                    if (j < 34) {
                        int xx = 2*j;
                        int gw = w0 + xx - 2;
                        float2 v = make_float2(0.f, 0.f);
                        if (hv) {
                            if (gw >= 0 && gw + 1 < WW) {
                                v = *(const float2*)&src[gh*WW + gw];
                            } else {
                                if (gw >= 0 && gw < WW)         v.x = src[gh*WW + gw];
                                if (gw + 1 >= 0 && gw + 1 < WW) v.y = src[gh*WW + gw + 1];
                            }
                        }
                        *(float2*)&st[c][yy][xx] = v;
                    }
                }
            }
        }
    }
}

// ---------------------------------------------------------------------------
// Kernel 4: partial similarities, 16-ch group, dy-outer, 2 px/thread.
// Exact round-9 configuration (regs=64, 4 blocks/SM).
// ---------------------------------------------------------------------------
__global__ __launch_bounds__(256,4) void k_sim() {
    __shared__ __align__(16) float st[GSIM][SHH][SHW];   // 52.2 KB

    int lane = threadIdx.x & 31;
    int warp = threadIdx.x >> 5;
    int w0 = blockIdx.x * STW;
    int h0 = blockIdx.y * STH;
    int g  = blockIdx.z & (NGRP-1);
    int n  = blockIdx.z >> 3;
    int c0 = g * GSIM;
    int h  = h0 + warp;
    int wA = w0 + 2*lane;
    int pixA = h*WW + wA;

    fill_tile(st, g_key, n*CH + c0, h0, w0, warp, lane);

    // q resident in regs (16 independent LDG.64)
    float2 q2[GSIM];
    #pragma unroll
    for (int c = 0; c < GSIM; c++)
        q2[c] = *(const float2*)&g_qry[((n*CH + c0 + c) << 14) + pixA];

    __syncthreads();

    #pragma unroll
    for (int dy = 0; dy < 5; dy++) {
        float sA[5], sB[5];
        #pragma unroll
        for (int t = 0; t < 5; t++) { sA[t] = 0.f; sB[t] = 0.f; }

        #pragma unroll
        for (int c = 0; c < GSIM; c++) {
            float2 t0 = *(float2*)&st[c][warp+dy][2*lane + 0];
            float2 t1 = *(float2*)&st[c][warp+dy][2*lane + 2];
            float2 t2 = *(float2*)&st[c][warp+dy][2*lane + 4];
            sA[0] += q2[c].x * t0.x;
            sA[1] += q2[c].x * t0.y;
            sA[2] += q2[c].x * t1.x;
            sA[3] += q2[c].x * t1.y;
            sA[4] += q2[c].x * t2.x;
            sB[0] += q2[c].y * t0.y;
            sB[1] += q2[c].y * t1.x;
            sB[2] += q2[c].y * t1.y;
            sB[3] += q2[c].y * t2.x;
            sB[4] += q2[c].y * t2.y;
        }

        #pragma unroll
        for (int dx = 0; dx < 5; dx++) {
            float2 o; o.x = sA[dx]; o.y = sB[dx];
            *(float2*)&g_psim[(((n*NGRP + g)*25 + dy*5 + dx) << 14) + pixA] = o;
        }
    }
}

// ---------------------------------------------------------------------------
// Kernel 5: fused gate + softmax. Per pixel:
//   dyn[o] = sigmoid(ba[o] + sum_sp sum_tap shift(s4))
//   w = dyn0 * softmax(sum_g psim);  w[12] += dyn1
// ---------------------------------------------------------------------------
__global__ __launch_bounds__(256) void k_smax(const float* __restrict__ ba) {
    int idx = blockIdx.x * 256 + threadIdx.x;     // (n, pix)
    int pix = idx & (PLANE-1);
    int n   = idx >> 14;
    int w = pix & (WW-1);
    int h = pix >> 7;

    // inline dyn computation (3x3 gather over 4 split partials, both outputs)
    float acc0 = ba[0];
    float acc1 = ba[1];
    #pragma unroll
    for (int sp = 0; sp < NSPLIT; sp++) {
        #pragma unroll
        for (int i = 0; i < 3; i++) {
            int hh = h + i - 1;
            if (hh < 0 || hh >= HH) continue;
            #pragma unroll
            for (int j = 0; j < 3; j++) {
                int ww2 = w + j - 1;
                if (ww2 < 0 || ww2 >= WW) continue;
                int t = i*3 + j;
                int off = hh*WW + ww2;
                acc0 += g_s4[((((sp*NB + n)*2 + 0)*9 + t) << 14) + off];
                acc1 += g_s4[((((sp*NB + n)*2 + 1)*9 + t) << 14) + off];
            }
        }
    }
    float d0 = 1.f / (1.f + __expf(-acc0));
    float d1 = 1.f / (1.f + __expf(-acc1));

    float s[25];
    #pragma unroll
    for (int k = 0; k < 25; k++) s[k] = 0.f;
    #pragma unroll
    for (int g = 0; g < NGRP; g++)
        #pragma unroll
        for (int k = 0; k < 25; k++)
            s[k] += g_psim[(((n*NGRP + g)*25 + k) << 14) + pix];

    float m = s[0];
    #pragma unroll
    for (int k = 1; k < 25; k++) m = fmaxf(m, s[k]);
    float ssum = 0.f;
    #pragma unroll
    for (int k = 0; k < 25; k++) { s[k] = __expf(s[k] - m); ssum += s[k]; }

    float scale = d0 / ssum;
    #pragma unroll
    for (int k = 0; k < 25; k++) {
        float wv = s[k] * scale;
        if (k == 12) wv += d1;
        g_w[((n*25 + k) << 14) + pix] = wv;
    }
}

// ---------------------------------------------------------------------------
// Kernel 6: value aggregation, dy-outer, 2 px/thread (round-9 configuration).
// ---------------------------------------------------------------------------
__global__ __launch_bounds__(256,4) void k_agg(float* __restrict__ out) {
    __shared__ __align__(16) float st[GSIM][SHH][SHW];   // 52.2 KB

    int lane = threadIdx.x & 31;
    int warp = threadIdx.x >> 5;
    int w0 = blockIdx.x * STW;
    int h0 = blockIdx.y * STH;
    int g  = blockIdx.z & (NGRP-1);
    int n  = blockIdx.z >> 3;
    int c0 = g * GSIM;
    int h  = h0 + warp;
    int wA = w0 + 2*lane;
    int pixA = h*WW + wA;

    fill_tile(st, g_val, n*CH + c0, h0, w0, warp, lane);

    float aA[GSIM], aB[GSIM];
    #pragma unroll
    for (int c = 0; c < GSIM; c++) { aA[c] = 0.f; aB[c] = 0.f; }

    __syncthreads();

    #pragma unroll
    for (int dy = 0; dy < 5; dy++) {
        float wgA[5], wgB[5];
        #pragma unroll
        for (int dx = 0; dx < 5; dx++) {
            float2 wv = *(const float2*)&g_w[((n*25 + dy*5 + dx) << 14) + pixA];
            wgA[dx] = wv.x; wgB[dx] = wv.y;
        }
        #pragma unroll
        for (int c = 0; c < GSIM; c++) {
            float2 t0 = *(float2*)&st[c][warp+dy][2*lane + 0];
            float2 t1 = *(float2*)&st[c][warp+dy][2*lane + 2];
            float2 t2 = *(float2*)&st[c][warp+dy][2*lane + 4];
            aA[c] += wgA[0]*t0.x + wgA[1]*t0.y + wgA[2]*t1.x + wgA[3]*t1.y + wgA[4]*t2.x;
            aB[c] += wgB[0]*t0.y + wgB[1]*t1.x + wgB[2]*t1.y + wgB[3]*t2.x + wgB[4]*t2.y;
        }
    }

    #pragma unroll
    for (int c = 0; c < GSIM; c++) {
        int gi = ((n*CH + c0 + c) << 14) + pixA;
        float2 lu = *(const float2*)&g_lrup[gi];
        float2 o; o.x = lu.x + aA[c]; o.y = lu.y + aB[c];
        *(float2*)&out[gi] = o;
    }
}

// ---------------------------------------------------------------------------
extern "C" void kernel_launch(void* const* d_in, const int* in_sizes, int n_in,
                              void* d_out, int out_size) {
    const float* hr = (const float*)d_in[0];
    const float* lr = (const float*)d_in[1];
    const float* wq = (const float*)d_in[2];
    const float* bq = (const float*)d_in[3];
    const float* wk = (const float*)d_in[4];
    const float* bk = (const float*)d_in[5];
    const float* wv = (const float*)d_in[6];
    const float* bv = (const float*)d_in[7];
    const float* wa = (const float*)d_in[8];
    const float* ba = (const float*)d_in[9];
    float* out = (float*)d_out;

    k_lrup<<<(NB*IMG)/256, 256>>>(lr);
    k_qkv <<<(NB*IMG/4)/128, 128>>>(hr, wq, bq, wk, bk, wv, bv);
    k_s   <<<dim3((NB*PLANE/2)/128, NSPLIT), 128>>>(wa);
    // k_sim stays 4th so the fixed ncu window lands on it
    k_sim <<<dim3(WW/STW, HH/STH, NB*NGRP), 256>>>();
    k_smax<<<(NB*PLANE)/256, 256>>>(ba);
    k_agg <<<dim3(WW/STW, HH/STH, NB*NGRP), 256>>>(out);
}

// round 15
// speedup vs baseline: 1.4887x; 1.1763x over previous
#include <cuda_runtime.h>
#include <cstdint>
#include <math.h>

// Problem constants (fixed shapes from setup_inputs)
#define NB 2
#define CH 128
#define HH 128
#define WW 128
#define HL 64
#define WL 64
#define PLANE (HH*WW)          // 16384
#define IMG   (CH*PLANE)

#define NSPLIT 4               // channel splits for gating conv
#define CPS (CH/NSPLIT)        // 32
#define NGRP 8                 // channel groups for sim/agg
#define GSIM (CH/NGRP)         // 16

// Scratch (module-load allocated; no runtime allocs)
__device__ float g_lrup[NB*IMG];
__device__ float g_key [NB*IMG];
__device__ float g_val [NB*IMG];
__device__ float g_qry [NB*IMG];
__device__ float g_s4  [NSPLIT*NB*2*9*PLANE];   // partial gating tap maps
__device__ float g_psim[NB*NGRP*25*PLANE];      // partial sims (26MB, L2-resident)
__device__ float g_w   [NB*25*PLANE];           // gated softmax weights

#define CP_COMMIT() asm volatile("cp.async.commit_group;")
#define CP_WAIT1()  asm volatile("cp.async.wait_group 1;")
#define CP_WAIT0()  asm volatile("cp.async.wait_group 0;")

// ---------------------------------------------------------------------------
// Kernel 1: bilinear upsample (align_corners=True) 64x64 -> 128x128
// ---------------------------------------------------------------------------
__global__ void k_lrup(const float* __restrict__ lr) {
    int idx = blockIdx.x * blockDim.x + threadIdx.x;
    int w  = idx & (WW-1);
    int h  = (idx >> 7) & (HH-1);
    int nc = idx >> 14;

    float ys = (float)(h * (HL-1)) / (float)(HH-1);
    float xs = (float)(w * (WL-1)) / (float)(WW-1);
    int y0 = (int)floorf(ys);
    int x0 = (int)floorf(xs);
    int y1 = min(y0 + 1, HL-1);
    int x1 = min(x0 + 1, WL-1);
    float wy = ys - (float)y0;
    float wx = xs - (float)x0;

    const float* p = lr + nc * (HL*WL);
    float a = p[y0*WL + x0];
    float b = p[y0*WL + x1];
    float c = p[y1*WL + x0];
    float d = p[y1*WL + x1];
    float top = a + (b - a) * wx;
    float bot = c + (d - c) * wx;
    g_lrup[idx] = top + (bot - top) * wy;
}

// ---------------------------------------------------------------------------
// Kernel 2: three depthwise 3x3 convs, 4 horizontal px/thread, float4 I/O.
// ---------------------------------------------------------------------------
__global__ __launch_bounds__(128) void k_qkv(const float* __restrict__ hr,
                      const float* __restrict__ wq, const float* __restrict__ bq,
                      const float* __restrict__ wk, const float* __restrict__ bk,
                      const float* __restrict__ wv, const float* __restrict__ bv) {
    int idx = blockIdx.x * 128 + threadIdx.x;   // (n, c, h, w4)
    int w4 = idx & 31;
    int h  = (idx >> 5) & (HH-1);
    int c  = (idx >> 12) & (CH-1);
    int n  = idx >> 19;
    int w0 = w4 * 4;

    const float* ph = hr     + (n*CH + c) * PLANE;
    const float* pl = g_lrup + (n*CH + c) * PLANE;

    float xh[3][6], xl[3][6];
    #pragma unroll
    for (int i = 0; i < 3; i++) {
        int hh = h + i - 1;
        bool hv = (hh >= 0) && (hh < HH);
        if (hv) {
            int rb = hh * WW;
            float lh = (w0 - 1 >= 0) ? ph[rb + w0 - 1] : 0.f;
            float ll = (w0 - 1 >= 0) ? pl[rb + w0 - 1] : 0.f;
            float4 mh = *(const float4*)&ph[rb + w0];
            float4 ml = *(const float4*)&pl[rb + w0];
            float rh = (w0 + 4 < WW) ? ph[rb + w0 + 4] : 0.f;
            float rl = (w0 + 4 < WW) ? pl[rb + w0 + 4] : 0.f;
            xh[i][0]=lh; xh[i][1]=mh.x; xh[i][2]=mh.y; xh[i][3]=mh.z; xh[i][4]=mh.w; xh[i][5]=rh;
            xl[i][0]=ll; xl[i][1]=ml.x; xl[i][2]=ml.y; xl[i][3]=ml.z; xl[i][4]=ml.w; xl[i][5]=rl;
        } else {
            #pragma unroll
            for (int j = 0; j < 6; j++) { xh[i][j] = 0.f; xl[i][j] = 0.f; }
        }
    }

    float wkr[9], wvr[9], wqr[9];
    #pragma unroll
    for (int t = 0; t < 9; t++) {
        wkr[t] = wk[c*9 + t];
        wvr[t] = wv[c*9 + t];
        wqr[t] = wq[c*9 + t];
    }
    float bkc = bk[c], bvc = bv[c], bqc = bq[c];

    float4 ok, ov, oq;
    float* okp = (float*)&ok; float* ovp = (float*)&ov; float* oqp = (float*)&oq;
    #pragma unroll
    for (int p = 0; p < 4; p++) {
        float acck = bkc, accv = bvc, accq = bqc;
        #pragma unroll
        for (int i = 0; i < 3; i++)
            #pragma unroll
            for (int j = 0; j < 3; j++) {
                acck += xh[i][p+j] * wkr[i*3+j];
                accv += xh[i][p+j] * wvr[i*3+j];
                accq += xl[i][p+j] * wqr[i*3+j];
            }
        okp[p] = acck; ovp[p] = accv; oqp[p] = accq;
    }
    int gi = ((n*CH + c) << 14) + h*WW + w0;
    *(float4*)&g_key[gi] = ok;
    *(float4*)&g_val[gi] = ov;
    *(float4*)&g_qry[gi] = oq;
}

// ---------------------------------------------------------------------------
// Kernel 3: partial gating tap maps, 4-way channel split, 2 px/thread.
// ---------------------------------------------------------------------------
__global__ __launch_bounds__(128) void k_s(const float* __restrict__ wa) {
    __shared__ __align__(16) float swa[CPS*36];   // 4.5 KB

    int tid = threadIdx.x;
    int sp  = blockIdx.y;
    int cbase = sp * CPS;

    for (int j = tid; j < CPS*36; j += 128) {
        int c   = j / 36;
        int r   = j % 36;
        int grp = r / 9;             // 0:q/o0 1:k/o0 2:q/o1 3:k/o1
        int t   = r % 9;
        int o   = grp >> 1;
        int ci  = cbase + c + ((grp & 1) ? CH : 0);
        swa[j] = wa[(o*2*CH + ci)*9 + t];
    }
    __syncthreads();

    int px0 = blockIdx.x * 256 + tid;           // pixel A
    int px1 = px0 + 128;                        // pixel B (same n: 256|16384)
    int n   = px0 >> 14;
    int pixA = px0 & (PLANE-1);
    int pixB = px1 & (PLANE-1);

    float accA[18], accB[18];
    #pragma unroll
    for (int t = 0; t < 18; t++) { accA[t] = 0.f; accB[t] = 0.f; }

    int baseA = n*CH*PLANE + cbase*PLANE + pixA;
    int baseB = n*CH*PLANE + cbase*PLANE + pixB;
    for (int c = 0; c < CPS; c++) {
        float qA = g_qry[baseA + c*PLANE];
        float kA = g_key[baseA + c*PLANE];
        float qB = g_qry[baseB + c*PLANE];
        float kB = g_key[baseB + c*PLANE];

        float wreg[36];
        float4* wr4 = (float4*)wreg;
        const float4* sw4 = (const float4*)(swa + c*36);
        #pragma unroll
        for (int i = 0; i < 9; i++) wr4[i] = sw4[i];

        #pragma unroll
        for (int t = 0; t < 9; t++) {
            accA[t]     += qA * wreg[t]    + kA * wreg[9+t];
            accA[9 + t] += qA * wreg[18+t] + kA * wreg[27+t];
            accB[t]     += qB * wreg[t]    + kB * wreg[9+t];
            accB[9 + t] += qB * wreg[18+t] + kB * wreg[27+t];
        }
    }

    #pragma unroll
    for (int o = 0; o < 2; o++)
        #pragma unroll
        for (int t = 0; t < 9; t++) {
            int s = (((sp*NB + n)*2 + o)*9 + t) << 14;
            g_s4[s + pixA] = accA[o*9 + t];
            g_s4[s + pixB] = accB[o*9 + t];
        }
}

// ---------------------------------------------------------------------------
// Tile geometry for window kernels: 64x8 px, 256 threads, warp = pixel row.
// SMEM column xx maps to gw = w0 + xx - 4  (halo of 4 on the left so every
// 16B cp.async is either fully in-range or fully out-of-range).
// ---------------------------------------------------------------------------
#define STW 64
#define STH 8
#define SHW 72        // 64 + 4 halo left + 4 halo right (float4-aligned)
#define SHH (STH+4)   // 12

// cp.async halo fill for an 8-channel chunk: 8*12 rows x 18 float4 = 1728 copies.
__device__ __forceinline__ void fill_async8(float st[GSIM][SHH][SHW],
                                            const float* gsrc, int nc_base,
                                            int cb, int h0, int w0, int tid) {
    const int NE = 8*12*18;
    #pragma unroll 1
    for (int i = tid; i < NE; i += 256) {
        int c  = i / 216;            // 12*18
        int r  = i - c*216;
        int yy = r / 18;
        int j  = r - yy*18;
        int gh = h0 + yy - 2;
        int gw = w0 + 4*j - 4;
        bool v = (gh >= 0) && (gh < HH) && (gw >= 0) && (gw < WW);
        int off = v ? (gh*WW + gw) : 0;
        const float* gp = gsrc + ((nc_base + cb + c) << 14) + off;
        uint32_t sa = (uint32_t)__cvta_generic_to_shared(&st[cb + c][yy][4*j]);
        int sz = v ? 16 : 0;
        asm volatile("cp.async.cg.shared.global [%0], [%1], 16, %2;"
                     :: "r"(sa), "l"(gp), "r"(sz));
    }
}

// ---------------------------------------------------------------------------
// Kernel 4: partial similarities, 16-ch group, dy-outer, 2 px/thread.
// cp.async fill (no fill registers, paced LSU), single wait, proven compute.
// ---------------------------------------------------------------------------
__global__ __launch_bounds__(256,4) void k_sim() {
    __shared__ __align__(16) float st[GSIM][SHH][SHW];   // 55.3 KB

    int tid  = threadIdx.x;
    int lane = tid & 31;
    int warp = tid >> 5;
    int w0 = blockIdx.x * STW;
    int h0 = blockIdx.y * STH;
    int g  = blockIdx.z & (NGRP-1);
    int n  = blockIdx.z >> 3;
    int c0 = g * GSIM;
    int pixA = (h0 + warp)*WW + w0 + 2*lane;

    fill_async8(st, g_key, n*CH + c0, 0, h0, w0, tid);
    CP_COMMIT();
    fill_async8(st, g_key, n*CH + c0, 8, h0, w0, tid);
    CP_COMMIT();

    // q loads overlap the async fills
    float2 q2[GSIM];
    #pragma unroll
    for (int c = 0; c < GSIM; c++)
        q2[c] = *(const float2*)&g_qry[((n*CH + c0 + c) << 14) + pixA];

    CP_WAIT0();
    __syncthreads();

    #pragma unroll
    for (int dy = 0; dy < 5; dy++) {
        float sA[5], sB[5];
        #pragma unroll
        for (int t = 0; t < 5; t++) { sA[t] = 0.f; sB[t] = 0.f; }

        #pragma unroll
        for (int c = 0; c < GSIM; c++) {
            float2 t0 = *(float2*)&st[c][warp+dy][2*lane + 2];
            float2 t1 = *(float2*)&st[c][warp+dy][2*lane + 4];
            float2 t2 = *(float2*)&st[c][warp+dy][2*lane + 6];
            sA[0] += q2[c].x * t0.x;
            sA[1] += q2[c].x * t0.y;
            sA[2] += q2[c].x * t1.x;
            sA[3] += q2[c].x * t1.y;
            sA[4] += q2[c].x * t2.x;
            sB[0] += q2[c].y * t0.y;
            sB[1] += q2[c].y * t1.x;
            sB[2] += q2[c].y * t1.y;
            sB[3] += q2[c].y * t2.x;
            sB[4] += q2[c].y * t2.y;
        }

        #pragma unroll
        for (int dx = 0; dx < 5; dx++) {
            float2 o; o.x = sA[dx]; o.y = sB[dx];
            *(float2*)&g_psim[(((n*NGRP + g)*25 + dy*5 + dx) << 14) + pixA] = o;
        }
    }
}

// ---------------------------------------------------------------------------
// Kernel 5: fused gate + softmax. Per pixel:
//   dyn[o] = sigmoid(ba[o] + sum_sp sum_tap shift(s4))
//   w = dyn0 * softmax(sum_g psim);  w[12] += dyn1
// ---------------------------------------------------------------------------
__global__ __launch_bounds__(128) void k_smax(const float* __restrict__ ba) {
    int idx = blockIdx.x * 128 + threadIdx.x;     // (n, pix)
    int pix = idx & (PLANE-1);
    int n   = idx >> 14;
    int w = pix & (WW-1);
    int h = pix >> 7;

    float acc0 = ba[0];
    float acc1 = ba[1];
    #pragma unroll
    for (int sp = 0; sp < NSPLIT; sp++) {
        #pragma unroll
        for (int i = 0; i < 3; i++) {
            int hh = h + i - 1;
            if (hh < 0 || hh >= HH) continue;
            #pragma unroll
            for (int j = 0; j < 3; j++) {
                int ww2 = w + j - 1;
                if (ww2 < 0 || ww2 >= WW) continue;
                int t = i*3 + j;
                int off = hh*WW + ww2;
                acc0 += g_s4[((((sp*NB + n)*2 + 0)*9 + t) << 14) + off];
                acc1 += g_s4[((((sp*NB + n)*2 + 1)*9 + t) << 14) + off];
            }
        }
    }
    float d0 = 1.f / (1.f + __expf(-acc0));
    float d1 = 1.f / (1.f + __expf(-acc1));

    float s[25];
    #pragma unroll
    for (int k = 0; k < 25; k++) s[k] = 0.f;
    #pragma unroll
    for (int g = 0; g < NGRP; g++)
        #pragma unroll
        for (int k = 0; k < 25; k++)
            s[k] += g_psim[(((n*NGRP + g)*25 + k) << 14) + pix];

    float m = s[0];
    #pragma unroll
    for (int k = 1; k < 25; k++) m = fmaxf(m, s[k]);
    float ssum = 0.f;
    #pragma unroll
    for (int k = 0; k < 25; k++) { s[k] = __expf(s[k] - m); ssum += s[k]; }

    float scale = d0 / ssum;
    #pragma unroll
    for (int k = 0; k < 25; k++) {
        float wv = s[k] * scale;
        if (k == 12) wv += d1;
        g_w[((n*25 + k) << 14) + pix] = wv;
    }
}

// ---------------------------------------------------------------------------
// Kernel 6: value aggregation, dy-outer, 2 px/thread, cp.async double buffer.
// ---------------------------------------------------------------------------
__device__ __forceinline__ void agg_chunk(const float st[GSIM][SHH][SHW], int cb,
                                          int n, int c0, int pixA,
                                          int warp, int lane,
                                          float* __restrict__ out) {
    float aA[8], aB[8];
    #pragma unroll
    for (int cc = 0; cc < 8; cc++) { aA[cc] = 0.f; aB[cc] = 0.f; }

    #pragma unroll
    for (int dy = 0; dy < 5; dy++) {
        float wgA[5], wgB[5];
        #pragma unroll
        for (int dx = 0; dx < 5; dx++) {
            float2 wv = *(const float2*)&g_w[((n*25 + dy*5 + dx) << 14) + pixA];
            wgA[dx] = wv.x; wgB[dx] = wv.y;
        }
        #pragma unroll
        for (int cc = 0; cc < 8; cc++) {
            int c = cb + cc;
            float2 t0 = *(const float2*)&st[c][warp+dy][2*lane + 2];
            float2 t1 = *(const float2*)&st[c][warp+dy][2*lane + 4];
            float2 t2 = *(const float2*)&st[c][warp+dy][2*lane + 6];
            aA[cc] += wgA[0]*t0.x + wgA[1]*t0.y + wgA[2]*t1.x + wgA[3]*t1.y + wgA[4]*t2.x;
            aB[cc] += wgB[0]*t0.y + wgB[1]*t1.x + wgB[2]*t1.y + wgB[3]*t2.x + wgB[4]*t2.y;
        }
    }

    #pragma unroll
    for (int cc = 0; cc < 8; cc++) {
        int gi = ((n*CH + c0 + cb + cc) << 14) + pixA;
        float2 lu = *(const float2*)&g_lrup[gi];
        float2 o; o.x = lu.x + aA[cc]; o.y = lu.y + aB[cc];
        *(float2*)&out[gi] = o;
    }
}

__global__ __launch_bounds__(256,4) void k_agg(float* __restrict__ out) {
    __shared__ __align__(16) float st[GSIM][SHH][SHW];   // 55.3 KB

    int tid  = threadIdx.x;
    int lane = tid & 31;
    int warp = tid >> 5;
    int w0 = blockIdx.x * STW;
    int h0 = blockIdx.y * STH;
    int g  = blockIdx.z & (NGRP-1);
    int n  = blockIdx.z >> 3;
    int c0 = g * GSIM;
    int pixA = (h0 + warp)*WW + w0 + 2*lane;

    fill_async8(st, g_val, n*CH + c0, 0, h0, w0, tid);
    CP_COMMIT();
    fill_async8(st, g_val, n*CH + c0, 8, h0, w0, tid);
    CP_COMMIT();

    CP_WAIT1();
    __syncthreads();
    agg_chunk(st, 0, n, c0, pixA, warp, lane, out);   // overlaps chunk-1 copies

    CP_WAIT0();
    __syncthreads();
    agg_chunk(st, 8, n, c0, pixA, warp, lane, out);
}

// ---------------------------------------------------------------------------
extern "C" void kernel_launch(void* const* d_in, const int* in_sizes, int n_in,
                              void* d_out, int out_size) {
    const float* hr = (const float*)d_in[0];
    const float* lr = (const float*)d_in[1];
    const float* wq = (const float*)d_in[2];
    const float* bq = (const float*)d_in[3];
    const float* wk = (const float*)d_in[4];
    const float* bk = (const float*)d_in[5];
    const float* wv = (const float*)d_in[6];
    const float* bv = (const float*)d_in[7];
    const float* wa = (const float*)d_in[8];
    const float* ba = (const float*)d_in[9];
    float* out = (float*)d_out;

    k_lrup<<<(NB*IMG)/256, 256>>>(lr);
    k_qkv <<<(NB*IMG/4)/128, 128>>>(hr, wq, bq, wk, bk, wv, bv);
    k_s   <<<dim3((NB*PLANE/2)/128, NSPLIT), 128>>>(wa);
    // k_sim stays 4th so the fixed ncu window lands on it
    k_sim <<<dim3(WW/STW, HH/STH, NB*NGRP), 256>>>();
    k_smax<<<(NB*PLANE)/128, 128>>>(ba);
    k_agg <<<dim3(WW/STW, HH/STH, NB*NGRP), 256>>>(out);
}